// round 5
// baseline (speedup 1.0000x reference)
#include <cuda_runtime.h>
#include <math.h>

#define TOTAL_V 991
#define BATCH   2048
#define NPARTS  20
#define NEPS    9

typedef unsigned long long ull;

__device__ __forceinline__ float ex2f_(float x){ float r; asm("ex2.approx.ftz.f32 %0, %1;" : "=f"(r) : "f"(x)); return r; }
__device__ __forceinline__ float lg2f_(float x){ float r; asm("lg2.approx.ftz.f32 %0, %1;" : "=f"(r) : "f"(x)); return r; }
__device__ __forceinline__ ull pack2_(float lo, float hi){ ull r; asm("mov.b64 %0, {%1, %2};" : "=l"(r) : "f"(lo), "f"(hi)); return r; }
__device__ __forceinline__ void unpack2_(ull v, float& lo, float& hi){ asm("mov.b64 {%0, %1}, %2;" : "=f"(lo), "=f"(hi) : "l"(v)); }
__device__ __forceinline__ ull fma2_(ull a, ull b, ull c){ ull r; asm("fma.rn.f32x2 %0, %1, %2, %3;" : "=l"(r) : "l"(a), "l"(b), "l"(c)); return r; }
__device__ __forceinline__ ull add2_(ull a, ull b){ ull r; asm("add.rn.f32x2 %0, %1, %2;" : "=l"(r) : "l"(a), "l"(b)); return r; }

__constant__ float c_eps[NEPS] = {64.f, 16.f, 4.f, 1.f, 0.25f, 0.0625f, 0.015625f, 0.00390625f, 0.0025f};

// Classes: K1 idx0..8 (n 40..45), K2 idx9..11 (n<=35), K3 idx12..15 (61..64),
//          K4 idx16..18 (50..60), K5 idx19 (92). {n, ld, soff, 0}; (ld/4) odd.
__constant__ int4 c_desc[NPARTS] = {
    {45,52,  0,0},{43,44,106,0},{45,52,149,0},{41,44,320,0},{44,44,423,0},
    {44,44,467,0},{42,44,569,0},{40,44,611,0},{41,44,711,0},
    {34,36,286,0},{35,36,752,0},{28,28,851,0},
    {61,68, 45,0},{62,68,361,0},{64,68,787,0},{62,68,929,0},
    {58,60,511,0},{60,60,651,0},{50,52,879,0},
    {92,92,194,0}
};

__device__ float g_scratch[NPARTS * BATCH];

// Fused two-pass partial logsumexp over `lim` float4s: z kept in packed-f32x2 regs.
template<int N4>
__device__ __forceinline__ void lse_part(const float4* __restrict__ r4,
                                         const float4* __restrict__ v4,
                                         int lim, ull nk2, float& Mr, float& Sr)
{
    ull z[2 * N4];
    float M0 = -3.0e38f, M1 = -3.0e38f, M2 = -3.0e38f, M3 = -3.0e38f;
    #pragma unroll
    for (int c = 0; c < N4; c++) if (c < lim) {
        float4 a = r4[c]; float4 w = v4[c];
        ull z01 = fma2_(pack2_(a.x, a.y), nk2, pack2_(w.x, w.y));
        ull z23 = fma2_(pack2_(a.z, a.w), nk2, pack2_(w.z, w.w));
        z[2*c] = z01; z[2*c+1] = z23;
        float zx, zy, zz, zw;
        unpack2_(z01, zx, zy); unpack2_(z23, zz, zw);
        M0 = fmaxf(M0, zx); M1 = fmaxf(M1, zy);
        M2 = fmaxf(M2, zz); M3 = fmaxf(M3, zw);
    }
    const float M = fmaxf(fmaxf(M0, M1), fmaxf(M2, M3));
    const ull nM2 = pack2_(-M, -M);
    float S0 = 0.f, S1 = 0.f, S2 = 0.f, S3 = 0.f;
    #pragma unroll
    for (int c = 0; c < N4; c++) if (c < lim) {
        float ax, ay, az, aw;
        unpack2_(add2_(z[2*c],   nM2), ax, ay);
        unpack2_(add2_(z[2*c+1], nM2), az, aw);
        S0 += ex2f_(ax); S1 += ex2f_(ay); S2 += ex2f_(az); S3 += ex2f_(aw);
    }
    Mr = M; Sr = (S0 + S1) + (S2 + S3);
}

// HALVES=1: thread (g,r), g=0..3 sweeps (f,g,px,py); one barrier per eps (double-buffered vecs).
// HALVES=2: thread (gg,r), gg=0..7, g=gg>>1, h=gg&1; each half sweeps half a row;
//           halves combine (M,S) via shared scratch; two barriers per eps.
// Pads: C=+1e30, vec=-1e30 -> z_pad huge-negative finite; fmax loses, ex2 FTZ->0.
template<int RS, int N4, int HALVES, int THREADS, int MINCTAS>
__global__ void __launch_bounds__(THREADS, MINCTAS)
sinkhorn_kernel(const float* __restrict__ pred, const float* __restrict__ pc, int first)
{
    const int pl = blockIdx.x >> 11;
    const int4 d = c_desc[first + pl];
    const int n = d.x, ld = d.y, soff = d.z;
    const int b = blockIdx.x & 2047;
    const int nc4 = ld >> 2;

    extern __shared__ float sm[];
    const int msz = n * ld;
    float* V  = sm + 4 * msz;          // 8 scaled (double-buffered) + 8 geometry
    float* xx = V + 8*ld;  float* xy = V + 9*ld;   float* xz = V + 10*ld;
    float* yx = V + 11*ld; float* yy = V + 12*ld;  float* yz = V + 13*ld;
    float* x2 = V + 14*ld; float* y2 = V + 15*ld;
    float* Msh = V + 16*ld;            // [8*RS] (HALVES==2 only)
    float* Ssh = Msh + 8*RS;

    const int t  = threadIdx.x;
    const int gg = t / RS;
    const int r  = t - gg * RS;
    const int g  = (HALVES == 2) ? (gg >> 1) : gg;
    const int h  = (HALVES == 2) ? (gg & 1) : 0;
    const bool act = (gg < 4 * HALVES) && (r < n);

    if (gg == 0 && r < n) {
        const float* X = pred + ((size_t)b * TOTAL_V + soff + r) * 3;
        float ax = X[0], ay = X[1], az = X[2];
        xx[r] = ax; xy[r] = ay; xz[r] = az;
        x2[r] = ax*ax + ay*ay + az*az;
    }
    if (gg == 1 && r < n) {
        const float* Y = pc + ((size_t)b * TOTAL_V + soff + r) * 3;
        float bx = Y[0], by = Y[1], bz = Y[2];
        yx[r] = bx; yy[r] = by; yz[r] = bz;
        y2[r] = bx*bx + by*by + bz*bz;
    }
    for (int j = n + t; j < ld; j += THREADS) {
        #pragma unroll
        for (int a = 0; a < 8; a++) V[a*ld + j] = -1e30f;
    }
    __syncthreads();

    // Build: (g,h) builds its half of row r of matrix g. g0:Cxy g1:Cyx g2:Cxx g3:Cyy
    const int lim = (HALVES == 2) ? (h ? (nc4 - N4) : N4) : nc4;   // float4s this thread owns
    const int cbase = (HALVES == 2) ? (h * N4) : 0;
    if (act) {
        const bool lX = (g == 0) || (g == 2);
        const bool rX = (g == 1) || (g == 2);
        const float lx = lX ? xx[r] : yx[r];
        const float ly = lX ? xy[r] : yy[r];
        const float lz = lX ? xz[r] : yz[r];
        const float hl2 = 0.5f * (lX ? x2[r] : y2[r]);
        const float4* ax4 = (const float4*)(rX ? xx : yx) + cbase;
        const float4* ay4 = (const float4*)(rX ? xy : yy) + cbase;
        const float4* az4 = (const float4*)(rX ? xz : yz) + cbase;
        const float4* a24 = (const float4*)(rX ? x2 : y2) + cbase;
        float4* row4 = (float4*)(sm + g*msz + r*ld) + cbase;
        #pragma unroll
        for (int c = 0; c < N4; c++) if (c < lim) {
            float4 ax = ax4[c], ay = ay4[c], az = az4[c], a2 = a24[c];
            float4 o;
            o.x = fmaf(-lx, ax.x, fmaf(-ly, ay.x, fmaf(-lz, az.x, fmaf(0.5f, a2.x, hl2))));
            o.y = fmaf(-lx, ax.y, fmaf(-ly, ay.y, fmaf(-lz, az.y, fmaf(0.5f, a2.y, hl2))));
            o.z = fmaf(-lx, ax.z, fmaf(-ly, ay.z, fmaf(-lz, az.z, fmaf(0.5f, a2.z, hl2))));
            o.w = fmaf(-lx, ax.w, fmaf(-ly, ay.w, fmaf(-lz, az.w, fmaf(0.5f, a2.w, hl2))));
            row4[c] = o;
        }
        if (h == HALVES - 1) {
            float* row = sm + g*msz + r*ld;
            for (int j = n; j < ld; j++) row[j] = 1e30f;   // overwrite tail garbage
        }
    }

    const float LOG2E = 1.44269504088896340736f;
    const float LN2   = 0.69314718055994530942f;
    const float l2n   = lg2f_((float)n);
    const int rg = (g < 2) ? (1 - g) : g;                 // vec each group reads
    const float4* rr = (const float4*)(sm + g*msz + r*ld) + cbase;

    float myv = 0.f;

    for (int e = 0; e < NEPS; e++) {
        const float eps = c_eps[e];
        const float k   = LOG2E / eps;
        const float nk  = -k;
        const ull   nk2 = pack2_(nk, nk);
        const float c1  = -eps * LN2;
        const float c2  = eps * LN2 * l2n;                // -eps*logb (loga == logb)

        if (act && h == 0) (V + ((e & 1) * 4 + g) * ld)[r] = myv * k;
        __syncthreads();

        float Mm, Sm;
        if (act) {
            const float4* vv = (const float4*)(V + ((e & 1) * 4 + rg) * ld) + cbase;
            lse_part<N4>(rr, vv, lim, nk2, Mm, Sm);
        }
        if (HALVES == 1) {
            if (act) myv = 0.5f * (myv + fmaf(c1, Mm + lg2f_(Sm), c2));
        } else {
            if (act) { Msh[gg*RS + r] = Mm; Ssh[gg*RS + r] = Sm; }
            __syncthreads();
            if (act) {
                const int peer = (gg ^ 1) * RS + r;
                const float Mo = Msh[peer], So = Ssh[peer];
                const float M = fmaxf(Mm, Mo);
                const float S = Sm * ex2f_(Mm - M) + So * ex2f_(Mo - M);
                myv = 0.5f * (myv + fmaf(c1, M + lg2f_(S), c2));
            }
        }
    }
    __syncthreads();   // protect V reuse as reduction scratch

    // div = (sum_f + sum_g - sum_px - sum_py)/n ; one contribution per (g,r): h==0 only
    float val = (act && h == 0) ? ((g < 2) ? myv : -myv) : 0.f;
    #pragma unroll
    for (int o = 16; o; o >>= 1) val += __shfl_xor_sync(0xffffffffu, val, o);
    if ((t & 31) == 0) V[t >> 5] = val;
    __syncthreads();
    if (t == 0) {
        float s = 0.f;
        const int nw = THREADS / 32;
        for (int w = 0; w < nw; w++) s += V[w];
        g_scratch[(first + pl) * BATCH + b] = s / (float)n;
    }
}

__global__ void reduce_kernel(float* __restrict__ out)
{
    __shared__ float red[32];
    float s = 0.f;
    for (int i = threadIdx.x; i < NPARTS * BATCH; i += 1024) s += g_scratch[i];
    #pragma unroll
    for (int o = 16; o; o >>= 1) s += __shfl_xor_sync(0xffffffffu, s, o);
    if ((threadIdx.x & 31) == 0) red[threadIdx.x >> 5] = s;
    __syncthreads();
    if (threadIdx.x < 32) {
        float v = red[threadIdx.x];
        #pragma unroll
        for (int o = 16; o; o >>= 1) v += __shfl_xor_sync(0xffffffffu, v, o);
        if (threadIdx.x == 0) out[0] = v * (1.0f / (float)BATCH);
    }
}

extern "C" void kernel_launch(void* const* d_in, const int* in_sizes, int n_in,
                              void* d_out, int out_size)
{
    const float* pred = (const float*)d_in[0];
    const float* pc   = (const float*)d_in[1];

    // smem = (4n + 16)*ld*4 (+ 16*RS*4 for HALVES=2 scratch), max per class
    const int smem1 = (4*45 + 16) * 52 * 4;                 // 40,768  x4 CTAs
    const int smem2 = (4*35 + 16) * 36 * 4;                 // 22,464  x6 CTAs
    const int smem3 = (4*64 + 16) * 68 * 4 + 16*64*4;       // 78,080  x2 CTAs (32 warps)
    const int smem4 = (4*60 + 16) * 60 * 4 + 16*64*4;       // 65,536  x2 CTAs (32 warps)
    const int smem5 = (4*92 + 16) * 92 * 4 + 16*96*4;       // 147,456 x1 CTA  (24 warps)

    cudaFuncSetAttribute((const void*)sinkhorn_kernel<45,13,1,192,4>, cudaFuncAttributeMaxDynamicSharedMemorySize, smem1);
    cudaFuncSetAttribute((const void*)sinkhorn_kernel<35, 9,1,160,6>, cudaFuncAttributeMaxDynamicSharedMemorySize, smem2);
    cudaFuncSetAttribute((const void*)sinkhorn_kernel<64, 9,2,512,2>, cudaFuncAttributeMaxDynamicSharedMemorySize, smem3);
    cudaFuncSetAttribute((const void*)sinkhorn_kernel<64, 8,2,512,2>, cudaFuncAttributeMaxDynamicSharedMemorySize, smem4);
    cudaFuncSetAttribute((const void*)sinkhorn_kernel<96,12,2,768,1>, cudaFuncAttributeMaxDynamicSharedMemorySize, smem5);

    sinkhorn_kernel<45,13,1,192,4><<<9 * BATCH, 192, smem1>>>(pred, pc,  0);
    sinkhorn_kernel<35, 9,1,160,6><<<3 * BATCH, 160, smem2>>>(pred, pc,  9);
    sinkhorn_kernel<64, 9,2,512,2><<<4 * BATCH, 512, smem3>>>(pred, pc, 12);
    sinkhorn_kernel<64, 8,2,512,2><<<3 * BATCH, 512, smem4>>>(pred, pc, 16);
    sinkhorn_kernel<96,12,2,768,1><<<1 * BATCH, 768, smem5>>>(pred, pc, 19);
    reduce_kernel<<<1, 1024>>>((float*)d_out);
}